// round 16
// baseline (speedup 1.0000x reference)
#include <cuda_runtime.h>
#include <cstdint>

#define BB 16
#define EE 128
#define CC 512
#define NCL 5
#define KITERS 8    // truncation 0.2^9/0.8 ~ 6.5e-7 << 1e-3 gate

// ---------------- device scratch (no allocations allowed) ----------------
__device__ float  g_part[4*BB*EE*EE];   // 4-way k-split partial Grams
__device__ double g_psum[128];
__device__ double g_psq[128];
__device__ int    g_lbl64;              // 1 if labels buffer is int64

// ---------------- f32x2 packed helpers (Blackwell) ----------------
__device__ __forceinline__ unsigned long long pk2(float a, float b) {
    unsigned long long r;
    asm("mov.b64 %0, {%1,%2};" : "=l"(r) : "f"(a), "f"(b));
    return r;
}
__device__ __forceinline__ void unpk2(unsigned long long v, float& lo, float& hi) {
    asm("mov.b64 {%0,%1}, %2;" : "=f"(lo), "=f"(hi) : "l"(v));
}
__device__ __forceinline__ void fma2(unsigned long long& acc,
                                     unsigned long long a, unsigned long long b) {
    asm("fma.rn.f32x2 %0, %1, %2, %0;" : "+l"(acc) : "l"(a), "l"(b));
}
__device__ __forceinline__ unsigned long long add2(unsigned long long a,
                                                   unsigned long long b) {
    unsigned long long r;
    asm("add.rn.f32x2 %0, %1, %2;" : "=l"(r) : "l"(a), "l"(b));
    return r;
}
__device__ __forceinline__ void cp_async8(unsigned smem, const void* g) {
    asm volatile("cp.async.ca.shared.global [%0], [%1], 8;" :: "r"(smem), "l"(g));
}

// ================= K1: partial Gram, 64x64 tile, 4x4/thread, f32x2 =====
// (round-15 version verbatim — 12.9us known-good)
__global__ void __launch_bounds__(256, 2) k_gram(const float* __restrict__ x,
                                                 const int* __restrict__ lab32) {
    __shared__ float2 sxi[2][64][16];
    __shared__ float2 sxj[2][64][16];
    int t  = threadIdx.x;
    int tx = t & 15, ty = t >> 4;
    int b  = blockIdx.z >> 2, kc = blockIdx.z & 3;
    int ib = blockIdx.y * 64, jb = blockIdx.x * 64;
    const float* xb = x + (size_t)b * EE * CC;

    // labels dtype detection (block 0 only): int64 => odd 32-bit words all 0
    if (blockIdx.x == 0 && blockIdx.y == 0 && blockIdx.z == 0) {
        __shared__ int sflag;
        if (t == 0) sflag = 0;
        __syncthreads();
        int v = 0;
        #pragma unroll
        for (int k = 0; k < 4; k++) v |= lab32[2*(t + 256*k) + 1];
        if (v) sflag = 1;
        __syncthreads();
        if (t == 0) g_lbl64 = (sflag == 0);
        __syncthreads();
    }

    unsigned si0 = (unsigned)__cvta_generic_to_shared(sxi);
    unsigned sj0 = (unsigned)__cvta_generic_to_shared(sxj);

    auto issue = [&](int buf, int sub) {
        int ch0 = kc * 128 + sub * 32;
        #pragma unroll
        for (int k = 0; k < 4; k++) {
            int idx = t + k * 256;
            int row = idx >> 4, c2 = idx & 15;
            int sw  = c2 ^ ((row >> 2) & 15);
            unsigned off = (unsigned)(((buf * 64 + row) * 16 + sw) * 8);
            cp_async8(si0 + off, &xb[(ib + row) * CC + ch0 + c2 * 2]);
            cp_async8(sj0 + off, &xb[(jb + row) * CC + ch0 + c2 * 2]);
        }
        asm volatile("cp.async.commit_group;");
    };

    unsigned long long acc[4][4];
    #pragma unroll
    for (int r = 0; r < 4; r++)
        #pragma unroll
        for (int s = 0; s < 4; s++) acc[r][s] = 0ull;

    issue(0, 0);
    #pragma unroll
    for (int sub = 0; sub < 4; sub++) {
        if (sub < 3) {
            issue((sub + 1) & 1, sub + 1);
            asm volatile("cp.async.wait_group 1;");
        } else {
            asm volatile("cp.async.wait_group 0;");
        }
        __syncthreads();
        int buf = sub & 1;
        #pragma unroll
        for (int c2 = 0; c2 < 16; c2++) {
            unsigned long long a2[4], b2[4];
            int ca = c2 ^ ty, cb = c2 ^ tx;
            #pragma unroll
            for (int r = 0; r < 4; r++) a2[r] = *(const unsigned long long*)&sxi[buf][4*ty + r][ca];
            #pragma unroll
            for (int s = 0; s < 4; s++) b2[s] = *(const unsigned long long*)&sxj[buf][4*tx + s][cb];
            #pragma unroll
            for (int r = 0; r < 4; r++)
                #pragma unroll
                for (int s = 0; s < 4; s++) fma2(acc[r][s], a2[r], b2[s]);
        }
        __syncthreads();
    }

    float* dst = g_part + (size_t)((kc * BB + b) * EE + ib + 4*ty) * EE + jb + 4*tx;
    #pragma unroll
    for (int r = 0; r < 4; r++) {
        float4 o;
        float lo, hi;
        unpk2(acc[r][0], lo, hi); o.x = lo + hi;
        unpk2(acc[r][1], lo, hi); o.y = lo + hi;
        unpk2(acc[r][2], lo, hi); o.z = lo + hi;
        unpk2(acc[r][3], lo, hi); o.w = lo + hi;
        *(float4*)(dst + (size_t)r * EE) = o;
    }
}

// ================= K2: stats partials only (no sq_dist write) ==========
// grid (8 rowgroups, 16 batches) = 128 blocks, 512 thr: warp = row.
// float4 loads: lane covers cols lane*4..lane*4+3 of its row, all 4 planes.
__global__ void __launch_bounds__(512) k_stats() {
    __shared__ float  diag[EE];
    __shared__ double sred[16], qred[16];
    int t = threadIdx.x;
    int b = blockIdx.y, rg = blockIdx.x;
    int w = t >> 5, lane = t & 31;
    int i = rg * 16 + w;
    const float rsc = 0.04419417382415922f;   // 1/sqrt(512)

    const float* gp0 = g_part + (size_t)(0*BB + b) * EE * EE;
    const float* gp1 = g_part + (size_t)(1*BB + b) * EE * EE;
    const float* gp2 = g_part + (size_t)(2*BB + b) * EE * EE;
    const float* gp3 = g_part + (size_t)(3*BB + b) * EE * EE;

    if (t < EE) {
        size_t d = (size_t)t * EE + t;
        diag[t] = (gp0[d] + gp1[d]) + (gp2[d] + gp3[d]);
    }
    __syncthreads();

    float ni = diag[i];
    size_t off = (size_t)i * EE + lane * 4;
    float4 G0 = *(const float4*)(gp0 + off);
    float4 G1 = *(const float4*)(gp1 + off);
    float4 G2 = *(const float4*)(gp2 + off);
    float4 G3 = *(const float4*)(gp3 + off);
    float  Gs[4] = { G0.x+G1.x+G2.x+G3.x, G0.y+G1.y+G2.y+G3.y,
                     G0.z+G1.z+G2.z+G3.z, G0.w+G1.w+G2.w+G3.w };
    double sm = 0.0, sq = 0.0;
    #pragma unroll
    for (int k = 0; k < 4; k++) {
        int j = lane * 4 + k;
        float sd = (ni + diag[j] - 2.f * Gs[k]) * rsc;
        if (j != i) { double d = sd; sm += d; sq += d * d; }
    }
    #pragma unroll
    for (int o = 16; o; o >>= 1) {
        sm += __shfl_xor_sync(0xffffffffu, sm, o);
        sq += __shfl_xor_sync(0xffffffffu, sq, o);
    }
    if (lane == 0) { sred[w] = sm; qred[w] = sq; }
    __syncthreads();
    if (w == 0) {
        double s2 = (lane < 16) ? sred[lane] : 0.0;
        double q2 = (lane < 16) ? qred[lane] : 0.0;
        #pragma unroll
        for (int o = 8; o; o >>= 1) {
            s2 += __shfl_xor_sync(0xffffffffu, s2, o);
            q2 += __shfl_xor_sync(0xffffffffu, q2, o);
        }
        if (lane == 0) { g_psum[b * 8 + rg] = s2; g_psq[b * 8 + rg] = q2; }
    }
}

// ================= K3: inline sd + weights + Neumann (per col-pair) ====
// grid (3 col-pairs, 16 batches) = 48 blocks, 256 threads: (row i, half h).
// sd recomputed from g_part columns (L2-resident) — no sq_dist buffer.
__global__ void __launch_bounds__(256)
k_prop(const int* __restrict__ lab32, float* __restrict__ out) {
    __shared__ float sh_inv;
    __shared__ __align__(16) float diag[EE];
    __shared__ __align__(16) float f[EE];
    __shared__ __align__(16) float rsp[2 * EE];
    __shared__ __align__(16) ulonglong2 v[EE];     // {c0,c1},{ones,pad}
    __shared__ __align__(16) ulonglong2 pbuf[EE];  // h1 -> h0 exchange
    int cp = blockIdx.x, b = blockIdx.y;
    int t = threadIdx.x;
    int i = t & 127, h = t >> 7;
    int base = h * 64;
    const float rsc = 0.04419417382415922f;   // 1/sqrt(512)

    const float* gp0 = g_part + (size_t)(0*BB + b) * EE * EE;
    const float* gp1 = g_part + (size_t)(1*BB + b) * EE * EE;
    const float* gp2 = g_part + (size_t)(2*BB + b) * EE * EE;
    const float* gp3 = g_part + (size_t)(3*BB + b) * EE * EE;

    if (t < EE) {
        size_t d = (size_t)t * EE + t;
        diag[t] = (gp0[d] + gp1[d]) + (gp2[d] + gp3[d]);
    }

    // ---- 1/std from the 128 double partials (warp 0) ----
    if (t < 32) {
        double s2 = g_psum[t] + g_psum[t + 32] + g_psum[t + 64] + g_psum[t + 96];
        double q2 = g_psq[t]  + g_psq[t + 32]  + g_psq[t + 64]  + g_psq[t + 96];
        #pragma unroll
        for (int o = 16; o; o >>= 1) {
            s2 += __shfl_xor_sync(0xffffffffu, s2, o);
            q2 += __shfl_xor_sync(0xffffffffu, q2, o);
        }
        if (t == 0) {
            const double cnt = (double)BB * EE * (EE - 1);     // mask = off-diagonal
            double var = (q2 - s2 * s2 / cnt) / (cnt - 1.0);   // Bessel (ddof=1)
            sh_inv = (float)(1.0 / sqrt(var));
        }
    }
    __syncthreads();
    float inv = sh_inv;
    float ni = diag[i];

    // ---- W column i, rows base..base+63 (coalesced over i; W symmetric) ----
    float s[64];
    float rs = 0.f;
    #pragma unroll
    for (int jj = 0; jj < 64; jj++) {
        int j = base + jj;
        size_t off = (size_t)j * EE + i;
        float G = (gp0[off] + gp1[off]) + (gp2[off] + gp3[off]);
        float sd = (ni + diag[j] - 2.f * G) * rsc;
        float wv = (j == i) ? 0.f : expf(-sd * inv);
        s[jj] = wv;
        rs += wv;
    }
    rsp[h * EE + i] = rs;   // partial column sum == partial row sum (symmetry)
    __syncthreads();
    if (t < EE) f[t] = 0.2f / (1e-4f + rsp[t] + rsp[EE + t]);   // alpha folded
    __syncthreads();
    #pragma unroll
    for (int jj = 0; jj < 64; jj++) s[jj] *= f[base + jj];      // aS entries

    // ---- init v = [onehot c0, onehot c1, ones] ----
    int c0 = 2 * cp, c1 = 2 * cp + 1;    // c1==5 means "ones" (cp==2)
    unsigned long long a01 = 0ull, a2 = 0ull;
    if (h == 0) {
        int lbl = g_lbl64 ? lab32[2*(b*EE + i)] : lab32[b*EE + i];
        float v0 = (lbl == c0) ? 1.f : 0.f;
        float v1 = (c1 < NCL) ? ((lbl == c1) ? 1.f : 0.f) : 1.f;
        a01 = pk2(v0, v1); a2 = pk2(1.f, 0.f);
        v[i].x = a01; v[i].y = a2;
    }
    __syncthreads();

    for (int it = 0; it < KITERS; it++) {
        unsigned long long p01 = 0ull, p2 = 0ull;
        #pragma unroll
        for (int jj = 0; jj < 64; jj++) {
            ulonglong2 w = v[base + jj];         // LDS.128, warp-broadcast
            unsigned long long ssp = pk2(s[jj], s[jj]);
            fma2(p01, ssp, w.x); fma2(p2, ssp, w.y);
        }
        if (h) pbuf[i] = make_ulonglong2(p01, p2);
        __syncthreads();
        if (h == 0) {
            ulonglong2 r = pbuf[i];
            p01 = add2(p01, r.x); p2 = add2(p2, r.y);
            a01 = add2(a01, p01); a2 = add2(a2, p2);
            v[i] = make_ulonglong2(p01, p2);
        }
        __syncthreads();   // v fully updated before next iteration reads it
    }

    if (h == 0) {
        float y0, y1, l1, dummy;
        unpk2(a01, y0, y1); unpk2(a2, l1, dummy);
        float invl = 1.f / fmaxf(l1, 1e-12f);
        float* o = out + (size_t)(b*EE + i) * NCL;
        o[c0] = logf(y0 * invl + 1e-6f);
        if (c1 < NCL) o[c1] = logf(y1 * invl + 1e-6f);
    }
}

// ================= launcher =================
extern "C" void kernel_launch(void* const* d_in, const int* in_sizes, int n_in,
                              void* d_out, int out_size) {
    const float* x   = (const float*)d_in[0];
    const int*   lab = (const int*)d_in[1];   // int32 or int64 — detected on device
    float*       out = (float*)d_out;

    k_gram<<<dim3(2, 2, 64), 256>>>(x, lab);
    k_stats<<<dim3(8, BB), 512>>>();
    k_prop<<<dim3(3, BB), 256>>>(lab, out);
}

// round 17
// speedup vs baseline: 1.7728x; 1.7728x over previous
#include <cuda_runtime.h>
#include <cstdint>

#define BB 16
#define EE 128
#define CC 512
#define NCL 5
#define KITERS 8    // truncation 0.2^9/0.8 ~ 6.5e-7 << 1e-3 gate

// ---------------- device scratch (no allocations allowed) ----------------
__device__ float  g_part[4*BB*EE*EE];   // 4-way k-split partial Grams
__device__ float  g_sqdist[BB*EE*EE];   // scaled sq_dist matrix
__device__ double g_psum[128];
__device__ double g_psq[128];
__device__ int    g_lbl64;              // 1 if labels buffer is int64

// ---------------- f32x2 packed helpers (Blackwell) ----------------
__device__ __forceinline__ unsigned long long pk2(float a, float b) {
    unsigned long long r;
    asm("mov.b64 %0, {%1,%2};" : "=l"(r) : "f"(a), "f"(b));
    return r;
}
__device__ __forceinline__ void unpk2(unsigned long long v, float& lo, float& hi) {
    asm("mov.b64 {%0,%1}, %2;" : "=f"(lo), "=f"(hi) : "l"(v));
}
__device__ __forceinline__ void fma2(unsigned long long& acc,
                                     unsigned long long a, unsigned long long b) {
    asm("fma.rn.f32x2 %0, %1, %2, %0;" : "+l"(acc) : "l"(a), "l"(b));
}
__device__ __forceinline__ unsigned long long add2(unsigned long long a,
                                                   unsigned long long b) {
    unsigned long long r;
    asm("add.rn.f32x2 %0, %1, %2;" : "=l"(r) : "l"(a), "l"(b));
    return r;
}
__device__ __forceinline__ void cp_async8(unsigned smem, const void* g) {
    asm volatile("cp.async.ca.shared.global [%0], [%1], 8;" :: "r"(smem), "l"(g));
}

// ================= K1: partial Gram, 64x64 tile, 4x4/thread, f32x2 =====
// (round-15 version verbatim — 12.9us known-good)
__global__ void __launch_bounds__(256, 2) k_gram(const float* __restrict__ x,
                                                 const int* __restrict__ lab32) {
    __shared__ float2 sxi[2][64][16];
    __shared__ float2 sxj[2][64][16];
    int t  = threadIdx.x;
    int tx = t & 15, ty = t >> 4;
    int b  = blockIdx.z >> 2, kc = blockIdx.z & 3;
    int ib = blockIdx.y * 64, jb = blockIdx.x * 64;
    const float* xb = x + (size_t)b * EE * CC;

    // labels dtype detection (block 0 only): int64 => odd 32-bit words all 0
    if (blockIdx.x == 0 && blockIdx.y == 0 && blockIdx.z == 0) {
        __shared__ int sflag;
        if (t == 0) sflag = 0;
        __syncthreads();
        int v = 0;
        #pragma unroll
        for (int k = 0; k < 4; k++) v |= lab32[2*(t + 256*k) + 1];
        if (v) sflag = 1;
        __syncthreads();
        if (t == 0) g_lbl64 = (sflag == 0);
        __syncthreads();
    }

    unsigned si0 = (unsigned)__cvta_generic_to_shared(sxi);
    unsigned sj0 = (unsigned)__cvta_generic_to_shared(sxj);

    auto issue = [&](int buf, int sub) {
        int ch0 = kc * 128 + sub * 32;
        #pragma unroll
        for (int k = 0; k < 4; k++) {
            int idx = t + k * 256;
            int row = idx >> 4, c2 = idx & 15;
            int sw  = c2 ^ ((row >> 2) & 15);
            unsigned off = (unsigned)(((buf * 64 + row) * 16 + sw) * 8);
            cp_async8(si0 + off, &xb[(ib + row) * CC + ch0 + c2 * 2]);
            cp_async8(sj0 + off, &xb[(jb + row) * CC + ch0 + c2 * 2]);
        }
        asm volatile("cp.async.commit_group;");
    };

    unsigned long long acc[4][4];
    #pragma unroll
    for (int r = 0; r < 4; r++)
        #pragma unroll
        for (int s = 0; s < 4; s++) acc[r][s] = 0ull;

    issue(0, 0);
    #pragma unroll
    for (int sub = 0; sub < 4; sub++) {
        if (sub < 3) {
            issue((sub + 1) & 1, sub + 1);
            asm volatile("cp.async.wait_group 1;");
        } else {
            asm volatile("cp.async.wait_group 0;");
        }
        __syncthreads();
        int buf = sub & 1;
        #pragma unroll
        for (int c2 = 0; c2 < 16; c2++) {
            unsigned long long a2[4], b2[4];
            int ca = c2 ^ ty, cb = c2 ^ tx;
            #pragma unroll
            for (int r = 0; r < 4; r++) a2[r] = *(const unsigned long long*)&sxi[buf][4*ty + r][ca];
            #pragma unroll
            for (int s = 0; s < 4; s++) b2[s] = *(const unsigned long long*)&sxj[buf][4*tx + s][cb];
            #pragma unroll
            for (int r = 0; r < 4; r++)
                #pragma unroll
                for (int s = 0; s < 4; s++) fma2(acc[r][s], a2[r], b2[s]);
        }
        __syncthreads();
    }

    float* dst = g_part + (size_t)((kc * BB + b) * EE + ib + 4*ty) * EE + jb + 4*tx;
    #pragma unroll
    for (int r = 0; r < 4; r++) {
        float4 o;
        float lo, hi;
        unpk2(acc[r][0], lo, hi); o.x = lo + hi;
        unpk2(acc[r][1], lo, hi); o.y = lo + hi;
        unpk2(acc[r][2], lo, hi); o.z = lo + hi;
        unpk2(acc[r][3], lo, hi); o.w = lo + hi;
        *(float4*)(dst + (size_t)r * EE) = o;
    }
}

// ================= K2: combine partials -> sq_dist + stats (float4) ====
// grid (8 rowgroups, 16 batches) = 128 blocks, 512 thr: warp = row,
// lane covers 4 CONSECUTIVE cols -> LDG.128 x4 + STG.128 x1 per thread.
__global__ void __launch_bounds__(512) k_sd() {
    __shared__ float  diag[EE];
    __shared__ double sred[16], qred[16];
    int t = threadIdx.x;
    int b = blockIdx.y, rg = blockIdx.x;
    int w = t >> 5, lane = t & 31;
    int i = rg * 16 + w;
    const float rsc = 0.04419417382415922f;   // 1/sqrt(512)

    const float* gp0 = g_part + (size_t)(0*BB + b) * EE * EE;
    const float* gp1 = g_part + (size_t)(1*BB + b) * EE * EE;
    const float* gp2 = g_part + (size_t)(2*BB + b) * EE * EE;
    const float* gp3 = g_part + (size_t)(3*BB + b) * EE * EE;

    if (t < EE) {
        size_t d = (size_t)t * EE + t;
        diag[t] = (gp0[d] + gp1[d]) + (gp2[d] + gp3[d]);
    }
    __syncthreads();

    float ni = diag[i];
    size_t off = (size_t)i * EE + lane * 4;
    float4 G0 = *(const float4*)(gp0 + off);
    float4 G1 = *(const float4*)(gp1 + off);
    float4 G2 = *(const float4*)(gp2 + off);
    float4 G3 = *(const float4*)(gp3 + off);
    float  Gs[4] = { G0.x+G1.x+G2.x+G3.x, G0.y+G1.y+G2.y+G3.y,
                     G0.z+G1.z+G2.z+G3.z, G0.w+G1.w+G2.w+G3.w };
    float  sd4[4];
    double sm = 0.0, sq = 0.0;
    #pragma unroll
    for (int k = 0; k < 4; k++) {
        int j = lane * 4 + k;
        float sd = (ni + diag[j] - 2.f * Gs[k]) * rsc;
        sd4[k] = sd;
        if (j != i) { double d = sd; sm += d; sq += d * d; }
    }
    *(float4*)(g_sqdist + (size_t)(b * EE + i) * EE + lane * 4) =
        make_float4(sd4[0], sd4[1], sd4[2], sd4[3]);

    #pragma unroll
    for (int o = 16; o; o >>= 1) {
        sm += __shfl_xor_sync(0xffffffffu, sm, o);
        sq += __shfl_xor_sync(0xffffffffu, sq, o);
    }
    if (lane == 0) { sred[w] = sm; qred[w] = sq; }
    __syncthreads();
    if (w == 0) {
        double s2 = (lane < 16) ? sred[lane] : 0.0;
        double q2 = (lane < 16) ? qred[lane] : 0.0;
        #pragma unroll
        for (int o = 8; o; o >>= 1) {
            s2 += __shfl_xor_sync(0xffffffffu, s2, o);
            q2 += __shfl_xor_sync(0xffffffffu, q2, o);
        }
        if (lane == 0) { g_psum[b * 8 + rg] = s2; g_psq[b * 8 + rg] = q2; }
    }
}

// ================= K3: stats + weights + Neumann (per column-pair) =====
// grid (3 col-pairs, 16 batches) = 48 blocks, 256 threads: (row i, half h).
// (round-15 version verbatim — known-good, no spills)
__global__ void __launch_bounds__(256)
k_prop(const int* __restrict__ lab32, float* __restrict__ out) {
    __shared__ float sh_inv;
    __shared__ __align__(16) float f[EE];
    __shared__ __align__(16) float rsp[2 * EE];
    __shared__ __align__(16) ulonglong2 v[EE];     // {c0,c1},{ones,pad}
    __shared__ __align__(16) ulonglong2 pbuf[EE];  // h1 -> h0 exchange
    int cp = blockIdx.x, b = blockIdx.y;
    int t = threadIdx.x;
    int i = t & 127, h = t >> 7;
    int base = h * 64;

    // ---- 1/std from the 128 double partials (warp 0) ----
    if (t < 32) {
        double s2 = g_psum[t] + g_psum[t + 32] + g_psum[t + 64] + g_psum[t + 96];
        double q2 = g_psq[t]  + g_psq[t + 32]  + g_psq[t + 64]  + g_psq[t + 96];
        #pragma unroll
        for (int o = 16; o; o >>= 1) {
            s2 += __shfl_xor_sync(0xffffffffu, s2, o);
            q2 += __shfl_xor_sync(0xffffffffu, q2, o);
        }
        if (t == 0) {
            const double cnt = (double)BB * EE * (EE - 1);     // mask = off-diagonal
            double var = (q2 - s2 * s2 / cnt) / (cnt - 1.0);   // Bessel (ddof=1)
            sh_inv = (float)(1.0 / sqrt(var));
        }
    }
    __syncthreads();
    float inv = sh_inv;

    // ---- W column i, rows base..base+63 (coalesced over i; W symmetric) ----
    const float* Sb = g_sqdist + (size_t)b * EE * EE;
    float s[64];
    float rs = 0.f;
    #pragma unroll
    for (int jj = 0; jj < 64; jj++) {
        int j = base + jj;
        float sd = Sb[(size_t)j * EE + i];
        float wv = (j == i) ? 0.f : expf(-sd * inv);
        s[jj] = wv;
        rs += wv;
    }
    rsp[h * EE + i] = rs;   // partial column sum == partial row sum (symmetry)
    __syncthreads();
    if (t < EE) f[t] = 0.2f / (1e-4f + rsp[t] + rsp[EE + t]);   // alpha folded
    __syncthreads();
    #pragma unroll
    for (int jj = 0; jj < 64; jj++) s[jj] *= f[base + jj];      // aS entries

    // ---- init v = [onehot c0, onehot c1, ones] ----
    int c0 = 2 * cp, c1 = 2 * cp + 1;    // c1==5 means "ones" (cp==2)
    unsigned long long a01 = 0ull, a2 = 0ull;
    if (h == 0) {
        int lbl = g_lbl64 ? lab32[2*(b*EE + i)] : lab32[b*EE + i];
        float v0 = (lbl == c0) ? 1.f : 0.f;
        float v1 = (c1 < NCL) ? ((lbl == c1) ? 1.f : 0.f) : 1.f;
        a01 = pk2(v0, v1); a2 = pk2(1.f, 0.f);
        v[i].x = a01; v[i].y = a2;
    }
    __syncthreads();

    for (int it = 0; it < KITERS; it++) {
        unsigned long long p01 = 0ull, p2 = 0ull;
        #pragma unroll
        for (int jj = 0; jj < 64; jj++) {
            ulonglong2 w = v[base + jj];         // LDS.128, warp-broadcast
            unsigned long long ssp = pk2(s[jj], s[jj]);
            fma2(p01, ssp, w.x); fma2(p2, ssp, w.y);
        }
        if (h) pbuf[i] = make_ulonglong2(p01, p2);
        __syncthreads();
        if (h == 0) {
            ulonglong2 r = pbuf[i];
            p01 = add2(p01, r.x); p2 = add2(p2, r.y);
            a01 = add2(a01, p01); a2 = add2(a2, p2);
            v[i] = make_ulonglong2(p01, p2);
        }
        __syncthreads();   // v fully updated before next iteration reads it
    }

    if (h == 0) {
        float y0, y1, l1, dummy;
        unpk2(a01, y0, y1); unpk2(a2, l1, dummy);
        float invl = 1.f / fmaxf(l1, 1e-12f);
        float* o = out + (size_t)(b*EE + i) * NCL;
        o[c0] = logf(y0 * invl + 1e-6f);
        if (c1 < NCL) o[c1] = logf(y1 * invl + 1e-6f);
    }
}

// ================= launcher =================
extern "C" void kernel_launch(void* const* d_in, const int* in_sizes, int n_in,
                              void* d_out, int out_size) {
    const float* x   = (const float*)d_in[0];
    const int*   lab = (const int*)d_in[1];   // int32 or int64 — detected on device
    float*       out = (float*)d_out;

    k_gram<<<dim3(2, 2, 64), 256>>>(x, lab);
    k_sd<<<dim3(8, BB), 512>>>();
    k_prop<<<dim3(3, BB), 256>>>(lab, out);
}